// round 2
// baseline (speedup 1.0000x reference)
#include <cuda_runtime.h>
#include <cuda_bf16.h>
#include <cstdint>

// Problem constants (match reference)
#define NDC 50000
#define NGC 100000
#define EC  600000
#define DIN 128
#define HD  64

// ---------------------------------------------------------------------------
// Scratch (static __device__ arrays; no dynamic allocation allowed)
// ---------------------------------------------------------------------------
__device__ float g_pd[(size_t)NDC * HD];   // disease Wl-projection (p_dg / layer2 pA)
__device__ float g_rd[(size_t)NDC * HD];   // disease Wr-projection (r_d1 / layer2 rA)
__device__ float g_pg[(size_t)NGC * HD];   // gene Wl-projection   (p_gd / layer2 pB)
__device__ float g_rg[(size_t)NGC * HD];   // gene Wr-projection   (r_g1 / layer2 rB)
__device__ float g_sumg[(size_t)NGC * HD]; // scatter accumulator into genes
__device__ float g_sumd[(size_t)NDC * HD]; // scatter accumulator into diseases
__device__ float g_cntg[NGC];
__device__ float g_cntd[NDC];
__device__ float g_d1[(size_t)NDC * HD];
__device__ float g_g1[(size_t)NGC * HD];

// ---------------------------------------------------------------------------
// Zero kernel (float4 grid-stride)
// ---------------------------------------------------------------------------
__global__ void zero_kernel(float* __restrict__ p, int n4) {
    int i = blockIdx.x * blockDim.x + threadIdx.x;
    int stride = gridDim.x * blockDim.x;
    for (; i < n4; i += stride) {
        ((float4*)p)[i] = make_float4(0.f, 0.f, 0.f, 0.f);
    }
}

// ---------------------------------------------------------------------------
// Degree count: cnt[dst[e]] += 1
// ---------------------------------------------------------------------------
__global__ void count_kernel(const int* __restrict__ dst, float* __restrict__ cnt, int E) {
    int e = blockIdx.x * blockDim.x + threadIdx.x;
    if (e < E) atomicAdd(&cnt[dst[e]], 1.0f);
}

// ---------------------------------------------------------------------------
// Dual-output projection GEMM: Y1 = X @ W1, Y2 = X @ W2
//   X: [N, K] row-major, W1/W2: [K, 64] row-major, Y: [N, 64]
// Block computes a 128-row x 128-col tile (cols 0-63 -> W1, 64-127 -> W2).
// 256 threads = 16x16, each with an 8x8 register micro-tile.
// ---------------------------------------------------------------------------
template <int K>
__global__ __launch_bounds__(256)
void proj2_kernel(const float* __restrict__ X,
                  const float* __restrict__ W1,
                  const float* __restrict__ W2,
                  float* __restrict__ Y1,
                  float* __restrict__ Y2,
                  int N)
{
    __shared__ float As[16][128];  // [k][row] (transposed)
    __shared__ float Bs[16][128];  // [k][col]

    const int tid = threadIdx.x;
    const int tx = tid & 15;       // col group (8 cols each)
    const int ty = tid >> 4;       // row group (8 rows each)
    const int rowBase = blockIdx.x * 128;

    float acc[8][8];
#pragma unroll
    for (int i = 0; i < 8; i++)
#pragma unroll
        for (int j = 0; j < 8; j++) acc[i][j] = 0.f;

    for (int k0 = 0; k0 < K; k0 += 16) {
        // Load A tile (128 rows x 16 k), transposed into As[k][row].
        // 512 float4 loads, 2 per thread.
#pragma unroll
        for (int i = 0; i < 2; i++) {
            int idx = tid + i * 256;      // 0..511
            int r   = idx >> 2;           // 0..127
            int kq  = idx & 3;            // float4 slot along k
            int row = rowBase + r;
            float4 v = make_float4(0.f, 0.f, 0.f, 0.f);
            if (row < N)
                v = *(const float4*)&X[(size_t)row * K + k0 + kq * 4];
            As[kq * 4 + 0][r] = v.x;
            As[kq * 4 + 1][r] = v.y;
            As[kq * 4 + 2][r] = v.z;
            As[kq * 4 + 3][r] = v.w;
        }
        // Load B tile: Bs[k][c] = (c<64 ? W1[k0+k][c] : W2[k0+k][c-64])
#pragma unroll
        for (int i = 0; i < 2; i++) {
            int idx = tid + i * 256;      // 0..511
            int k   = idx >> 5;           // 0..15
            int cq  = idx & 31;           // float4 slot over 128 cols
            const float* Wsrc = (cq < 16) ? W1 : W2;
            int c = (cq < 16) ? (cq * 4) : ((cq - 16) * 4);
            float4 v = *(const float4*)&Wsrc[(size_t)(k0 + k) * 64 + c];
            *(float4*)&Bs[k][cq * 4] = v;
        }
        __syncthreads();

#pragma unroll
        for (int k = 0; k < 16; k++) {
            float a[8], b[8];
            *(float4*)&a[0] = *(float4*)&As[k][ty * 8];
            *(float4*)&a[4] = *(float4*)&As[k][ty * 8 + 4];
            *(float4*)&b[0] = *(float4*)&Bs[k][tx * 8];
            *(float4*)&b[4] = *(float4*)&Bs[k][tx * 8 + 4];
#pragma unroll
            for (int i = 0; i < 8; i++)
#pragma unroll
                for (int j = 0; j < 8; j++) acc[i][j] = fmaf(a[i], b[j], acc[i][j]);
        }
        __syncthreads();
    }

    // Epilogue: each thread's 8 cols fall entirely in one of the two outputs.
    float* Y = (tx < 8) ? Y1 : Y2;
    int c = (tx < 8) ? (tx * 8) : (tx * 8 - 64);
#pragma unroll
    for (int i = 0; i < 8; i++) {
        int row = rowBase + ty * 8 + i;
        if (row < N) {
            *(float4*)&Y[(size_t)row * 64 + c]     = *(float4*)&acc[i][0];
            *(float4*)&Y[(size_t)row * 64 + c + 4] = *(float4*)&acc[i][4];
        }
    }
}

// ---------------------------------------------------------------------------
// Scatter-add: SUM[dst[e]] += P[src[e]]  (64 floats per edge)
// One thread per (edge, 4-float chunk): E*16 threads, vector red.global.add.
// ---------------------------------------------------------------------------
__global__ __launch_bounds__(256)
void scatter_kernel(const float* __restrict__ P,
                    const int* __restrict__ src,
                    const int* __restrict__ dst,
                    float* __restrict__ SUM,
                    int E)
{
    int idx = blockIdx.x * blockDim.x + threadIdx.x;
    if (idx >= E * 16) return;
    int e = idx >> 4;
    int c = (idx & 15) << 2;
    int s = __ldg(&src[e]);
    int d = __ldg(&dst[e]);
    float4 v = *(const float4*)&P[(size_t)s * 64 + c];
    float* p = &SUM[(size_t)d * 64 + c];
    asm volatile("red.global.add.v4.f32 [%0], {%1, %2, %3, %4};"
                 :: "l"(p), "f"(v.x), "f"(v.y), "f"(v.z), "f"(v.w)
                 : "memory");
}

// ---------------------------------------------------------------------------
// Combine: OUT[i] = SUM[i]/max(cnt[i],1) + bias + R[i]
// One thread per (node, 4-float chunk).
// ---------------------------------------------------------------------------
__global__ __launch_bounds__(256)
void combine_kernel(const float* __restrict__ SUM,
                    const float* __restrict__ CNT,
                    const float* __restrict__ bias,
                    const float* __restrict__ R,
                    float* __restrict__ OUT,
                    int N)
{
    int idx = blockIdx.x * blockDim.x + threadIdx.x;
    if (idx >= N * 16) return;
    int i = idx >> 4;
    int c = (idx & 15) << 2;
    float inv = 1.0f / fmaxf(__ldg(&CNT[i]), 1.0f);
    float4 s = *(const float4*)&SUM[(size_t)i * 64 + c];
    float4 r = *(const float4*)&R[(size_t)i * 64 + c];
    float4 b = *(const float4*)&bias[c];
    float4 o;
    o.x = fmaf(s.x, inv, b.x + r.x);
    o.y = fmaf(s.y, inv, b.y + r.y);
    o.z = fmaf(s.z, inv, b.z + r.z);
    o.w = fmaf(s.w, inv, b.w + r.w);
    *(float4*)&OUT[(size_t)i * 64 + c] = o;
}

// ---------------------------------------------------------------------------
// Host orchestration
// ---------------------------------------------------------------------------
extern "C" void kernel_launch(void* const* d_in, const int* in_sizes, int n_in,
                              void* d_out, int out_size)
{
    const float* x_d    = (const float*)d_in[0];
    const float* x_g    = (const float*)d_in[1];
    const int*   src_dg = (const int*)d_in[2];
    const int*   dst_dg = (const int*)d_in[3];
    const int*   src_gd = (const int*)d_in[4];
    const int*   dst_gd = (const int*)d_in[5];
    const float* Wl1_dg = (const float*)d_in[6];
    const float* bl1_dg = (const float*)d_in[7];
    const float* Wr1_dg = (const float*)d_in[8];
    const float* Wl1_gd = (const float*)d_in[9];
    const float* bl1_gd = (const float*)d_in[10];
    const float* Wr1_gd = (const float*)d_in[11];
    const float* Wl2_dg = (const float*)d_in[12];
    const float* bl2_dg = (const float*)d_in[13];
    const float* Wr2_dg = (const float*)d_in[14];
    const float* Wl2_gd = (const float*)d_in[15];
    const float* bl2_gd = (const float*)d_in[16];
    const float* Wr2_gd = (const float*)d_in[17];
    float* out = (float*)d_out;

    const int nd = in_sizes[0] / DIN;   // 50000
    const int ng = in_sizes[1] / DIN;   // 100000
    const int E  = in_sizes[2];         // 600000

    float *pd, *rd, *pg, *rg, *sumg, *sumd, *cntg, *cntd, *d1, *g1;
    cudaGetSymbolAddress((void**)&pd,   g_pd);
    cudaGetSymbolAddress((void**)&rd,   g_rd);
    cudaGetSymbolAddress((void**)&pg,   g_pg);
    cudaGetSymbolAddress((void**)&rg,   g_rg);
    cudaGetSymbolAddress((void**)&sumg, g_sumg);
    cudaGetSymbolAddress((void**)&sumd, g_sumd);
    cudaGetSymbolAddress((void**)&cntg, g_cntg);
    cudaGetSymbolAddress((void**)&cntd, g_cntd);
    cudaGetSymbolAddress((void**)&d1,   g_d1);
    cudaGetSymbolAddress((void**)&g1,   g_g1);

    const int ZB = 256;
    auto zgrid = [](int n4) { int g = (n4 + 255) / 256; return g > 8192 ? 8192 : g; };

    // ---- zero accumulators + counts ----
    zero_kernel<<<zgrid(ng * 16), ZB>>>(sumg, ng * 16);
    zero_kernel<<<zgrid(nd * 16), ZB>>>(sumd, nd * 16);
    zero_kernel<<<zgrid(ng / 4),  ZB>>>(cntg, ng / 4);
    zero_kernel<<<zgrid(nd / 4),  ZB>>>(cntd, nd / 4);

    // ---- degree counts (shared by both layers) ----
    count_kernel<<<(E + 255) / 256, 256>>>(dst_dg, cntg, E);
    count_kernel<<<(E + 255) / 256, 256>>>(dst_gd, cntd, E);

    // ---- layer 1 projections (project-then-scatter: mean@Wl == scatter(x@Wl)/cnt) ----
    proj2_kernel<DIN><<<(nd + 127) / 128, 256>>>(x_d, Wl1_dg, Wr1_gd, pd, rd, nd);
    proj2_kernel<DIN><<<(ng + 127) / 128, 256>>>(x_g, Wl1_gd, Wr1_dg, pg, rg, ng);

    // ---- layer 1 scatter ----
    {
        int threads = E * 16;
        scatter_kernel<<<(threads + 255) / 256, 256>>>(pd, src_dg, dst_dg, sumg, E);
        scatter_kernel<<<(threads + 255) / 256, 256>>>(pg, src_gd, dst_gd, sumd, E);
    }

    // ---- layer 1 combine: g1, d1 ----
    combine_kernel<<<(ng * 16 + 255) / 256, 256>>>(sumg, cntg, bl1_dg, rg, g1, ng);
    combine_kernel<<<(nd * 16 + 255) / 256, 256>>>(sumd, cntd, bl1_gd, rd, d1, nd);

    // ---- layer 2 projections (K=64) ----
    proj2_kernel<HD><<<(nd + 127) / 128, 256>>>(d1, Wl2_dg, Wr2_gd, pd, rd, nd);
    proj2_kernel<HD><<<(ng + 127) / 128, 256>>>(g1, Wl2_gd, Wr2_dg, pg, rg, ng);

    // ---- re-zero accumulators ----
    zero_kernel<<<zgrid(ng * 16), ZB>>>(sumg, ng * 16);
    zero_kernel<<<zgrid(nd * 16), ZB>>>(sumd, nd * 16);

    // ---- layer 2 scatter ----
    {
        int threads = E * 16;
        scatter_kernel<<<(threads + 255) / 256, 256>>>(pd, src_dg, dst_dg, sumg, E);
        scatter_kernel<<<(threads + 255) / 256, 256>>>(pg, src_gd, dst_gd, sumd, E);
    }

    // ---- layer 2 combine into output: d2 first, then g2 ----
    combine_kernel<<<(nd * 16 + 255) / 256, 256>>>(sumd, cntd, bl2_gd, rd, out, nd);
    combine_kernel<<<(ng * 16 + 255) / 256, 256>>>(sumg, cntg, bl2_dg, rg, out + (size_t)nd * 64, ng);
}